// round 10
// baseline (speedup 1.0000x reference)
#include <cuda_runtime.h>
#include <cuda_fp16.h>
#include <math.h>

#define B_ 16
#define T_ 512
#define D_ 256
#define H_ 8
#define E_ 32
#define BASIS_ 8
#define HB_ 128          // H_*B_

// ---------------- scratch (static device globals; no allocation) ----------------
__device__ float   g_qw[T_*BASIS_];
__device__ float   g_kw[T_*BASIS_];
__device__ __half2 g_Qb16[BASIS_*D_*128];  // 1MB fp16 basis [kd][e]
__device__ __half2 g_Kb16[BASIS_*D_*128];
__device__ float   g_q[HB_*T_*E_];         // [h][b][t][e] fp32
__device__ float   g_k[HB_*T_*E_];
__device__ __half2 g_v16[HB_*T_*E_/2];     // [h][b][t][e] fp16
__device__ __half2 g_lamA2[T_*256];
__device__ __half2 g_oml2[T_*256];

// ---------------- mma / ldmatrix helpers (validated R7) ----------------
__device__ __forceinline__ void ldsm_x4(unsigned &r0, unsigned &r1, unsigned &r2, unsigned &r3,
                                        unsigned addr) {
    asm volatile("ldmatrix.sync.aligned.m8n8.x4.shared.b16 {%0,%1,%2,%3},[%4];"
                 : "=r"(r0), "=r"(r1), "=r"(r2), "=r"(r3) : "r"(addr));
}
__device__ __forceinline__ void ldsm_x4t(unsigned &r0, unsigned &r1, unsigned &r2, unsigned &r3,
                                         unsigned addr) {
    asm volatile("ldmatrix.sync.aligned.m8n8.x4.trans.shared.b16 {%0,%1,%2,%3},[%4];"
                 : "=r"(r0), "=r"(r1), "=r"(r2), "=r"(r3) : "r"(addr));
}
__device__ __forceinline__ void mma16816(float* d, unsigned a0, unsigned a1, unsigned a2,
                                         unsigned a3, unsigned b0, unsigned b1) {
    asm volatile("mma.sync.aligned.m16n8k16.row.col.f32.f16.f16.f32 "
                 "{%0,%1,%2,%3},{%4,%5,%6,%7},{%8,%9},{%0,%1,%2,%3};"
                 : "+f"(d[0]), "+f"(d[1]), "+f"(d[2]), "+f"(d[3])
                 : "r"(a0), "r"(a1), "r"(a2), "r"(a3), "r"(b0), "r"(b1));
}

// ---------------- K0: basis fp32 -> fp16 ----------------
__global__ void k0_basis(const float* __restrict__ Qb, const float* __restrict__ Kb) {
    int ix = blockIdx.x * 256 + threadIdx.x;
    const float* src = blockIdx.y ? Kb : Qb;
    __half2* dst = blockIdx.y ? g_Kb16 : g_Qb16;
    float2 f = ((const float2*)src)[ix];
    dst[ix] = __floats2half2_rn(f.x, f.y);
}

// ---------------- K1: per-token basis mixing weights ----------------
__global__ void k1_weights(const float* __restrict__ te,
                           const float* __restrict__ Wq,
                           const float* __restrict__ Wk) {
    int t = blockIdx.x;
    int warp = threadIdx.x >> 5, lane = threadIdx.x & 31;
    const float* tr = te + t * D_;
    const float* wq = Wq + (t * BASIS_ + warp) * D_;
    const float* wk = Wk + (t * BASIS_ + warp) * D_;
    float aq = 0.f, ak = 0.f;
    #pragma unroll
    for (int m = 0; m < D_ / 32; ++m) {
        int d = lane + 32 * m;
        float x = tr[d];
        aq += x * wq[d];
        ak += x * wk[d];
    }
    #pragma unroll
    for (int o = 16; o; o >>= 1) {
        aq += __shfl_xor_sync(0xffffffffu, aq, o);
        ak += __shfl_xor_sync(0xffffffffu, ak, o);
    }
    if (lane == 0) {
        g_qw[t * BASIS_ + warp] = aq;
        g_kw[t * BASIS_ + warp] = ak;
    }
}

// ---------------- K23: q/k projections as HMMA GEMM, K=2048 over (basis k, d) ----------------
// C[row=(t,b), e] = sum_{k,d} qw[t,k] * X[b,t,d] * basis[k*256+d, e]
// CTA: 64 rows (4 t x 16 b) x 64 cols.  A = X fp16 tile (per-k reuse), fold qw in fp32.
__global__ __launch_bounds__(256) void k23_qk(const float* __restrict__ X) {
    extern __shared__ char s23[];
    __half* Xs  = (__half*)s23;              // [64][264] fp16, 33792 B
    __half* Bsm = (__half*)(s23 + 33792);    // [2][64][72] fp16, 18432 B
    float*  qws = (float*)(s23 + 52224);     // [4][8]

    int tid = threadIdx.x;
    int t0 = blockIdx.x << 2;
    int ntile = blockIdx.y;      // 0..3 -> e cols [64*ntile, +64)
    int side = blockIdx.z;       // 0=q, 1=k
    const __half* Bg = side ? (const __half*)g_Kb16 : (const __half*)g_Qb16;
    const float* qwg = side ? g_kw : g_qw;
    float* Out = side ? g_k : g_q;

    if (tid < 32) qws[tid] = qwg[(t0 + (tid >> 3)) * 8 + (tid & 7)];

    // X rows -> fp16 Xs; row = (t0 + row>>4, b = row&15)
    for (int idx = tid; idx < 4096; idx += 256) {
        int row = idx >> 6, f4 = idx & 63;
        int t = t0 + (row >> 4), b = row & 15;
        float4 xv = *(const float4*)&X[((size_t)(b * T_ + t) << 8) + (f4 << 2)];
        __half2 p0 = __floats2half2_rn(xv.x, xv.y);
        __half2 p1 = __floats2half2_rn(xv.z, xv.w);
        uint2 u;
        u.x = *(const unsigned*)&p0;
        u.y = *(const unsigned*)&p1;
        *(uint2*)&Xs[row * 264 + (f4 << 2)] = u;
    }

    // prefetch + store B chunk 0: rows kd in [0,64), cols [ntile*64, +64)
    uint4 br[2];
    #pragma unroll
    for (int i = 0; i < 2; ++i) {
        int u = tid + (i << 8);
        int r = u >> 3, c8 = u & 7;
        br[i] = *(const uint4*)&Bg[(r << 8) + (ntile << 6) + (c8 << 3)];
    }
    #pragma unroll
    for (int i = 0; i < 2; ++i) {
        int u = tid + (i << 8);
        int r = u >> 3, c8 = u & 7;
        *(uint4*)&Bsm[r * 72 + (c8 << 3)] = br[i];
    }
    __syncthreads();

    int warp = tid >> 5, lane = tid & 31;
    int wm = warp & 3, wn = warp >> 2;   // warp tile: rows [wm*16,+16) = t0+wm, cols [wn*32,+32)

    float master[4][4], part[4][4];
    #pragma unroll
    for (int f = 0; f < 4; ++f)
        #pragma unroll
        for (int j = 0; j < 4; ++j) { master[f][j] = 0.f; part[f][j] = 0.f; }

    unsigned sb;
    asm("{ .reg .u64 t; cvta.to.shared.u64 t, %1; cvt.u32.u64 %0, t; }" : "=r"(sb) : "l"(s23));
    unsigned axbase = sb + (unsigned)((wm * 16 + (lane & 15)) * 528 + ((lane >> 4) << 4));
    unsigned bxbase = sb + 33792u + (unsigned)((lane & 15) * 144 + wn * 64 + ((lane >> 4) << 4));

    for (int kc = 0; kc < 32; ++kc) {
        if (kc + 1 < 32) {
            #pragma unroll
            for (int i = 0; i < 2; ++i) {
                int u = tid + (i << 8);
                int r = u >> 3, c8 = u & 7;
                br[i] = *(const uint4*)&Bg[(((kc + 1) * 64 + r) << 8) + (ntile << 6) + (c8 << 3)];
            }
        }
        unsigned acol = (unsigned)((kc & 3) * 128);         // d-block byte offset
        unsigned bbuf = (unsigned)((kc & 1) * 9216);
        #pragma unroll
        for (int ks = 0; ks < 4; ++ks) {
            unsigned a0, a1, a2, a3, b0, b1, b2, b3;
            ldsm_x4(a0, a1, a2, a3, axbase + acol + ks * 32);
            ldsm_x4t(b0, b1, b2, b3, bxbase + bbuf + ks * 2304);
            mma16816(part[0], a0, a1, a2, a3, b0, b1);
            mma16816(part[1], a0, a1, a2, a3, b2, b3);
            ldsm_x4t(b0, b1, b2, b3, bxbase + bbuf + ks * 2304 + 32);
            mma16816(part[2], a0, a1, a2, a3, b0, b1);
            mma16816(part[3], a0, a1, a2, a3, b2, b3);
        }
        if ((kc & 3) == 3) {   // fold k-group with fp32 qw
            float s = qws[wm * 8 + (kc >> 2)];
            #pragma unroll
            for (int f = 0; f < 4; ++f)
                #pragma unroll
                for (int j = 0; j < 4; ++j) { master[f][j] += s * part[f][j]; part[f][j] = 0.f; }
        }
        if (kc + 1 < 32) {
            #pragma unroll
            for (int i = 0; i < 2; ++i) {
                int u = tid + (i << 8);
                int r = u >> 3, c8 = u & 7;
                *(uint4*)&Bsm[((kc + 1) & 1) * 4608 + r * 72 + (c8 << 3)] = br[i];
            }
        }
        __syncthreads();
    }

    // epilogue: scatter master frags to [h][b][t][e] fp32
    int b_lo = lane >> 2, b_hi = b_lo + 8;
    int t = t0 + wm;
    #pragma unroll
    for (int f = 0; f < 4; ++f) {
        int e = (ntile << 6) + (wn << 5) + (f << 3) + ((lane & 3) << 1);
        int h = e >> 5, eo = e & 31;
        *(float2*)&Out[((size_t)((h * B_ + b_lo) * T_ + t) << 5) + eo]
            = make_float2(master[f][0], master[f][1]);
        *(float2*)&Out[((size_t)((h * B_ + b_hi) * T_ + t) << 5) + eo]
            = make_float2(master[f][2], master[f][3]);
    }
}

// ---------------- K3v: v projection (fp32 W -> fp16 out) ----------------
__global__ __launch_bounds__(256) void k3_v(const float* __restrict__ X,
                                            const float* __restrict__ WV) {
    __shared__ float xsT[D_][16];
    int t = blockIdx.x, m = blockIdx.y;   // m in 0,1: col halves

    for (int idx = threadIdx.x; idx < B_ * D_; idx += 256) {
        int b = idx >> 8, d = idx & 255;
        xsT[d][b] = X[((size_t)b * T_ + t) * D_ + d];
    }
    __syncthreads();

    int tc = threadIdx.x & 31;
    int tb = threadIdx.x >> 5;
    float acc[2][4];
    #pragma unroll
    for (int i = 0; i < 2; ++i)
        #pragma unroll
        for (int j = 0; j < 4; ++j) acc[i][j] = 0.f;
    int e0 = (m << 7) + (tc << 2);
    const float* W = WV + (size_t)t * 65536;
    #pragma unroll 8
    for (int d = 0; d < D_; ++d) {
        float2 xv = *(const float2*)&xsT[d][tb << 1];
        float4 wv = *(const float4*)&W[(d << 8) + e0];
        acc[0][0] += xv.x * wv.x; acc[0][1] += xv.x * wv.y;
        acc[0][2] += xv.x * wv.z; acc[0][3] += xv.x * wv.w;
        acc[1][0] += xv.y * wv.x; acc[1][1] += xv.y * wv.y;
        acc[1][2] += xv.y * wv.z; acc[1][3] += xv.y * wv.w;
    }
    int h = e0 >> 5, eo = e0 & 31;
    #pragma unroll
    for (int i = 0; i < 2; ++i) {
        int b = (tb << 1) + i;
        __half2 h0 = __floats2half2_rn(acc[i][0], acc[i][1]);
        __half2 h1 = __floats2half2_rn(acc[i][2], acc[i][3]);
        uint2 u;
        u.x = *(const unsigned int*)&h0;
        u.y = *(const unsigned int*)&h1;
        *(uint2*)&g_v16[(((size_t)(h * B_ + b) * T_ + t) << 4) + (eo >> 1)] = u;
    }
}

// ---------------- K4: mixing coefficients (half2 out) ----------------
__global__ void k4_mix(const float* __restrict__ A, const float* __restrict__ L) {
    int t = blockIdx.x, c = threadIdx.x;
    int j0 = c << 1, j1 = j0 + 1;
    float a0 = 0.5f * (A[t * T_ + j0] + A[j0 * T_ + t]);
    float a1 = 0.5f * (A[t * T_ + j1] + A[j1 * T_ + t]);
    float lam0 = 1.0f / (1.0f + __expf(-L[t * T_ + j0]));
    float lam1 = 1.0f / (1.0f + __expf(-L[t * T_ + j1]));
    g_lamA2[t * 256 + c] = __floats2half2_rn(lam0 * a0, lam1 * a1);
    g_oml2[t * 256 + c]  = __floats2half2_rn(1.0f - lam0, 1.0f - lam1);
}

// ---------------- K57: fused scores+softmax+mix+symexp+Sinkhorn+PV ----------------
#define SM_UNION 131072
#define SM_Y     196864
#define SM_UL    200960
#define SMEM57   201472
#define NW_      32

#define CBAR() do { \
    asm volatile("barrier.cluster.arrive.aligned;" ::: "memory"); \
    asm volatile("barrier.cluster.wait.aligned;"  ::: "memory"); } while (0)

__global__ __launch_bounds__(1024) __cluster_dims__(4, 1, 1)
void k57(float* __restrict__ out) {
    extern __shared__ char sm[];
    __half2* tile = (__half2*)sm;                 // [128][256] half2
    float2*  kT2  = (float2*)(sm + SM_UNION);     // [32][257] float2
    float*   Vs   = (float*)(sm + SM_UNION);      // [512][32] f32
    float*   s_y  = (float*)(sm + SM_Y);          // [2][512]
    float*   s_ul = (float*)(sm + SM_UL);         // [128]

    int tid = threadIdx.x;
    int hb = blockIdx.x >> 2;
    int rank = blockIdx.x & 3;
    int warp = tid >> 5, lane = tid & 31;

    unsigned sbase;
    asm("{ .reg .u64 t; cvta.to.shared.u64 t, %1; cvt.u32.u64 %0, t; }"
        : "=r"(sbase) : "l"(sm));

    // ---- phase 1: K transpose into kT2 ----
    const float* K = g_k + hb * (T_ * E_);
    for (int idx = tid; idx < T_ * E_; idx += 1024) {
        int t = idx >> 5, e = idx & 31;
        ((float*)&kT2[e * 257 + (t >> 1)])[t & 1] = K[idx];
    }
    __syncthreads();

    // ---- phase 2: scores + softmax + mix -> tile ----
    {
        const float* Q = g_q + hb * (T_ * E_);
        const float SC = 0.17677669529663687f;
        for (int p = warp; p < 64; p += NW_) {
            int i0 = p << 1, i1 = i0 + 1;
            int gi0 = (rank << 7) + i0, gi1 = gi0 + 1;
            float q0 = Q[(gi0 << 5) + lane];
            float q1 = Q[(gi1 << 5) + lane];
            float a[8][4];
            #pragma unroll
            for (int m = 0; m < 8; ++m) { a[m][0] = a[m][1] = a[m][2] = a[m][3] = 0.f; }
            #pragma unroll
            for (int d = 0; d < 32; ++d) {
                float qd0 = __shfl_sync(0xffffffffu, q0, d);
                float qd1 = __shfl_sync(0xffffffffu, q1, d);
                const float2* row = &kT2[d * 257];
                #pragma unroll
                for (int m = 0; m < 8; ++m) {
                    float2 kv = row[lane + (m << 5)];
                    a[m][0] += qd0 * kv.x; a[m][1] += qd0 * kv.y;
                    a[m][2] += qd1 * kv.x; a[m][3] += qd1 * kv.y;
                }
            }
            float mx0 = -1e30f, mx1 = -1e30f;
            #pragma unroll
            for (int m = 0; m < 8; ++m) {
                a[m][0] *= SC; a[m][1] *= SC; a[m][2] *= SC; a[m][3] *= SC;
                mx0 = fmaxf(mx0, fmaxf(a[m][0], a[m][1]));
                mx1 = fmaxf(mx1, fmaxf(a[m][2], a[m][3]));
            }
            #pragma unroll
            for (int o = 16; o; o >>= 1) {
                mx0 = fmaxf(mx0, __shfl_xor_sync(0xffffffffu, mx0, o));
                mx1 = fmaxf(mx1, __shfl_xor_sync(0xffffffffu, mx1, o));
            }
            float sm0 = 0.f, sm1 = 0.f;
            #pragma unroll
            for (int m = 0; m < 8; ++m) {
                a[m][0] = __expf(a[m][0] - mx0); a[m][1] = __expf(a[m][1] - mx0);
                a[m][2] = __expf(a[m][2] - mx1); a[m][3] = __expf(a[m][3] - mx1);
                sm0 += a[m][0] + a[m][1];
                sm1 += a[m][2] + a[m][3];
            }
            #pragma unroll
            for (int o = 16; o; o >>= 1) {
                sm0 += __shfl_xor_sync(0xffffffffu, sm0, o);
                sm1 += __shfl_xor_sync(0xffffffffu, sm1, o);
            }
            float in0 = 1.0f / sm0, in1 = 1.0f / sm1;
            #pragma unroll
            for (int m = 0; m < 8; ++m) {
                int c = lane + (m << 5);
                float2 la0 = __half22float2(g_lamA2[gi0 * 256 + c]);
                float2 om0 = __half22float2(g_oml2[gi0 * 256 + c]);
                float2 la1 = __half22float2(g_lamA2[gi1 * 256 + c]);
                float2 om1 = __half22float2(g_oml2[gi1 * 256 + c]);
                tile[(i0 << 8) + c] = __floats2half2_rn(la0.x + om0.x * (a[m][0] * in0),
                                                        la0.y + om0.y * (a[m][1] * in0));
                tile[(i1 << 8) + c] = __floats2half2_rn(la1.x + om1.x * (a[m][2] * in1),
                                                        la1.y + om1.y * (a[m][3] * in1));
            }
        }
    }
    __syncthreads();
    CBAR();

    // ---- phase 3: symmetrize + exp (DSMEM peer reads) ----
    {
        int i0 = (tid & 15) << 3;
        int j0 = (tid >> 4) << 3;
        uint4 pv[8];
        #pragma unroll
        for (int jj = 0; jj < 8; ++jj) {
            int j = j0 + jj;
            unsigned laddr = sbase + (unsigned)((((j & 127) << 9) + (rank << 7) + i0) << 1);
            unsigned raddr;
            asm volatile("mapa.shared::cluster.u32 %0, %1, %2;"
                         : "=r"(raddr) : "r"(laddr), "r"(j >> 7));
            asm volatile("ld.shared::cluster.v4.u32 {%0,%1,%2,%3}, [%4];"
                         : "=r"(pv[jj].x), "=r"(pv[jj].y), "=r"(pv[jj].z), "=r"(pv[jj].w)
                         : "r"(raddr));
        }
        CBAR();
        #pragma unroll
        for (int ii = 0; ii < 8; ++ii) {
            int i = i0 + ii;
            __half2* rowp = &tile[(i << 8) + (j0 >> 1)];
            uint4 o0 = *(const uint4*)rowp;
            __half oh[8];
            *(uint4*)&oh[0] = o0;
            __half rh[8];
            #pragma unroll
            for (int jj = 0; jj < 8; ++jj) {
                float pe = __half2float(((const __half*)&pv[jj])[ii]);
                float ow = __half2float(oh[jj]);
                rh[jj] = __float2half_rn(__expf(0.5f * (ow + pe)));
            }
            *(uint4*)rowp = *(const uint4*)&rh[0];
        }
    }
    if (tid < 512) s_y[tid] = 1.0f;
    __syncthreads();

    // ---- phase 4: Sinkhorn, 40 half-steps ----
    int cur = 0;
    for (int hstep = 0; hstep < 40; ++hstep) {
        const float* yb = &s_y[cur << 9];
        float4 ya0 = *(const float4*)&yb[lane * 8];
        float4 ya1 = *(const float4*)&yb[lane * 8 + 4];
        float4 yb0 = *(const float4*)&yb[256 + lane * 8];
        float4 yb1 = *(const float4*)&yb[256 + lane * 8 + 4];
        __half2 yh0 = __floats2half2_rn(ya0.x, ya0.y);
        __half2 yh1 = __floats2half2_rn(ya0.z, ya0.w);
        __half2 yh2 = __floats2half2_rn(ya1.x, ya1.y);
        __half2 yh3 = __floats2half2_rn(ya1.z, ya1.w);
        __half2 yh4 = __floats2half2_rn(yb0.x, yb0.y);
        __half2 yh5 = __floats2half2_rn(yb0.z, yb0.w);
        __half2 yh6 = __floats2half2_rn(yb1.x, yb1.y);
        __half2 yh7 = __floats2half2_rn(yb1.z, yb1.w);

        int nxt = cur ^ 1;
        for (int i = warp; i < 128; i += NW_) {
            const uint4* rowq = (const uint4*)(tile + (i << 8));
            uint4 ea = rowq[lane];
            uint4 eb = rowq[lane + 32];
            __half2 a0 = __hmul2(*(const __half2*)&ea.x, yh0);
            a0 = __hfma2(*(const __half2*)&ea.y, yh1, a0);
            a0 = __hfma2(*(const __half2*)&ea.z, yh2, a0);
            a0 = __hfma2(*(const __half2*)&ea.w, yh3, a0);
            __half2 a1 = __hmul2(*(const __half2*)&eb.x, yh4);
            a1 = __hfma2(*(const __half2*)&eb.y, yh5, a1);
            a1 = __hfma2(*(const __half2*)&eb.z, yh6, a1);
            a1 = __hfma2(*(const __half2*)&eb.w, yh7, a1);
            float2 f0 = __half22float2(a0);
            float2 f1 = __half22float2(a1);
            float acc = f0.x + f0.y + f1.x + f1.y;
            #pragma unroll
            for (int o = 16; o; o >>= 1) acc += __shfl_xor_sync(0xffffffffu, acc, o);
            if (lane == 0) {
                float r = 1.0f / acc;
                if (!(hstep & 1)) s_ul[i] = r;
                unsigned laddr = sbase + (unsigned)(SM_Y + (((nxt << 9) + (rank << 7) + i) << 2));
                #pragma unroll
                for (int tr = 0; tr < 4; ++tr) {
                    unsigned raddr;
                    asm volatile("mapa.shared::cluster.u32 %0, %1, %2;"
                                 : "=r"(raddr) : "r"(laddr), "r"(tr));
                    asm volatile("st.shared::cluster.f32 [%0], %1;"
                                 :: "r"(raddr), "f"(r) : "memory");
                }
            }
        }
        CBAR();
        cur ^= 1;
    }

    // ---- phase 5: Vs fp32 = V * ev ----
    {
        const __half2* V16 = g_v16 + hb * 8192;
        const float* evf = &s_y[cur << 9];
        for (int idx = tid; idx < 8192; idx += 1024) {
            int j = idx >> 4, c2 = idx & 15;
            float2 v = __half22float2(V16[idx]);
            float e = evf[j];
            Vs[(j << 5) + (c2 << 1)]     = v.x * e;
            Vs[(j << 5) + (c2 << 1) + 1] = v.y * e;
        }
    }
    __syncthreads();

    // ---- phase 6: out = eu * (E @ Vs), 4 rows per warp ----
    {
        float acc[4];
        #pragma unroll
        for (int r = 0; r < 4; ++r) acc[r] = 0.f;
        const __half2* trow = tile + ((warp << 2) << 8);
        #pragma unroll 2
        for (int c = 0; c < 256; ++c) {
            float vx = Vs[((c << 1) << 5) + lane];
            float vy = Vs[(((c << 1) + 1) << 5) + lane];
            #pragma unroll
            for (int r = 0; r < 4; ++r) {
                float2 p = __half22float2(trow[(r << 8) + c]);
                acc[r] += p.x * vx + p.y * vy;
            }
        }
        int h = hb >> 4, b = hb & 15;
        #pragma unroll
        for (int r = 0; r < 4; ++r) {
            int gi = (rank << 7) + (warp << 2) + r;
            out[(((size_t)(b * T_ + gi)) << 8) + (h << 5) + lane]
                = s_ul[(warp << 2) + r] * acc[r];
        }
    }
}

// ---------------- launch ----------------
extern "C" void kernel_launch(void* const* d_in, const int* in_sizes, int n_in,
                              void* d_out, int out_size) {
    const float* X  = (const float*)d_in[0];
    const float* te = (const float*)d_in[1];
    const float* Wq = (const float*)d_in[2];
    const float* Wk = (const float*)d_in[3];
    const float* Qb = (const float*)d_in[4];
    const float* Kb = (const float*)d_in[5];
    const float* WV = (const float*)d_in[6];
    const float* A  = (const float*)d_in[7];
    const float* L  = (const float*)d_in[8];
    float* out = (float*)d_out;

    const int smem23 = 52352;
    cudaFuncSetAttribute(k23_qk, cudaFuncAttributeMaxDynamicSharedMemorySize, smem23);
    cudaFuncSetAttribute(k57,    cudaFuncAttributeMaxDynamicSharedMemorySize, SMEM57);

    k0_basis<<<dim3(1024, 2), 256>>>(Qb, Kb);
    k1_weights<<<T_, 256>>>(te, Wq, Wk);
    k23_qk<<<dim3(128, 4, 2), 256, smem23>>>(X);
    k3_v<<<dim3(T_, 2), 256>>>(X, WV);
    k4_mix<<<T_, 256>>>(A, L);
    k57<<<HB_ * 4, 1024, SMEM57>>>(out);
}